// round 1
// baseline (speedup 1.0000x reference)
#include <cuda_runtime.h>
#include <cuda_bf16.h>

#define BB 4
#define NN 10000
#define MM 10000
#define PP 128
#define KS 32
#define ZF 128

// ---------------- device scratch (static: no allocation) ----------------
__device__ float4 g_noisy4[BB * NN];      // (x,y,z, x^2+y^2+z^2)
__device__ float4 g_clean4[BB * MM];
__device__ float4 g_forigin[BB * PP];
__device__ float  g_zpart[BB * PP * ZF];  // Ws1[3:]^T z + bs1 per (b,p)
__device__ float4 g_fpts[BB * PP * KS];   // gathered noisy neighbors
__device__ float  g_estim[BB * PP * KS * 3];
__device__ float  g_partial[BB * PP];

__device__ __forceinline__ float finf() { return __int_as_float(0x7f800000); }

// ---------------- K0: pack point clouds as float4 with |r|^2 ----------------
__global__ void k0_pack(const float* __restrict__ noisy, const float* __restrict__ clean) {
    int i = blockIdx.x * blockDim.x + threadIdx.x;
    if (i < BB * NN) {
        float x = noisy[i * 3 + 0], y = noisy[i * 3 + 1], z = noisy[i * 3 + 2];
        g_noisy4[i] = make_float4(x, y, z, fmaf(x, x, fmaf(y, y, z * z)));
    }
    if (i < BB * MM) {
        float x = clean[i * 3 + 0], y = clean[i * 3 + 1], z = clean[i * 3 + 2];
        g_clean4[i] = make_float4(x, y, z, fmaf(x, x, fmaf(y, y, z * z)));
    }
}

// ---------------- K1: f_origin, feat(sampled), zpart ----------------
__global__ void k1_feat(const float* __restrict__ noisy, const int* __restrict__ sidx,
                        const float* __restrict__ Wf1, const float* __restrict__ bf1,
                        const float* __restrict__ Wf2, const float* __restrict__ bf2,
                        const float* __restrict__ Ws1, const float* __restrict__ bs1) {
    int bp = blockIdx.x;            // 0..511
    int b = bp >> 7, p = bp & 127;
    int tid = threadIdx.x;          // 128 threads
    __shared__ float xyz[3];
    __shared__ float h[64];
    __shared__ float z[128];

    if (tid == 0) {
        int si = sidx[p];
        const float* s = noisy + ((size_t)b * NN + si) * 3;
        xyz[0] = s[0]; xyz[1] = s[1]; xyz[2] = s[2];
        g_forigin[bp] = make_float4(s[0], s[1], s[2], 0.f);
    }
    __syncthreads();

    if (tid < 64) {
        float a = bf1[tid];
        a = fmaf(xyz[0], Wf1[0 * 64 + tid], a);
        a = fmaf(xyz[1], Wf1[1 * 64 + tid], a);
        a = fmaf(xyz[2], Wf1[2 * 64 + tid], a);
        h[tid] = fmaxf(a, 0.f);
    }
    __syncthreads();

    {
        float a = bf2[tid];
#pragma unroll 16
        for (int i = 0; i < 64; ++i) a = fmaf(h[i], Wf2[i * 128 + tid], a);
        z[tid] = a;                 // feat: no relu on second layer
    }
    __syncthreads();

    {
        float a = bs1[tid];
#pragma unroll 16
        for (int i = 0; i < 128; ++i) a = fmaf(z[i], Ws1[(3 + i) * 128 + tid], a);
        g_zpart[bp * ZF + tid] = a;
    }
}

// ---------------- K2: KNN1 top-32 via threshold binary search ----------------
__global__ __launch_bounds__(256) void k2_knn1() {
    int bp = blockIdx.x;            // one query per block
    int b = bp >> 7;
    int tid = threadIdx.x;
    __shared__ unsigned keys[NN];   // 40 KB
    __shared__ unsigned s_cnt;

    float4 q = g_forigin[bp];
    for (int r = tid; r < NN; r += 256) {
        float4 v = g_noisy4[b * NN + r];
        float dot = fmaf(q.z, v.z, fmaf(q.y, v.y, q.x * v.x));
        float s = fmaf(dot, -2.0f, v.w);          // d2 - |q|^2 (monotone in d2)
        unsigned u = __float_as_uint(s);
        u ^= ((unsigned)((int)u >> 31)) | 0x80000000u;  // monotone float->uint
        keys[r] = u;
    }
    __syncthreads();

    unsigned lo = 0u, hi = 0xFFFFFFFFu;
    for (int it = 0; it < 34 && lo + 1u < hi; ++it) {
        unsigned mid = lo + ((hi - lo) >> 1);
        if (tid == 0) s_cnt = 0;
        __syncthreads();
        unsigned c = 0;
        for (int r = tid; r < NN; r += 256) c += (keys[r] <= mid);
        c = __reduce_add_sync(0xFFFFFFFFu, c);
        if ((tid & 31) == 0) atomicAdd(&s_cnt, c);
        __syncthreads();
        unsigned cnt = s_cnt;
        __syncthreads();
        if (cnt >= 32u) { hi = mid; if (cnt == 32u) break; }
        else lo = mid;
    }
    unsigned T = hi;   // count(keys <= T) >= 32 (== 32 for distinct values)

    if (tid == 0) s_cnt = 0;
    __syncthreads();
    for (int r = tid; r < NN; r += 256) {
        if (keys[r] <= T) {
            unsigned pos = atomicAdd(&s_cnt, 1u);
            if (pos < 32u) g_fpts[bp * KS + pos] = g_noisy4[b * NN + r];
        }
    }
}

// ---------------- K3: score MLP (factored layer 1) ----------------
__global__ __launch_bounds__(128) void k3_mlp(const float* __restrict__ Ws1,
                                              const float* __restrict__ Ws2,
                                              const float* __restrict__ bs2,
                                              const float* __restrict__ Ws3,
                                              const float* __restrict__ bs3) {
    int bp = blockIdx.x;
    int tid = threadIdx.x;          // 128 threads
    __shared__ float xs[KS][4];
    __shared__ float h1s[KS * 129]; // padded rows: conflict-free
    __shared__ float h2s[KS * 68];

    float4 o4 = g_forigin[bp];
    if (tid < 32) {
        float4 f = g_fpts[bp * KS + tid];
        xs[tid][0] = f.x - o4.x;
        xs[tid][1] = f.y - o4.y;
        xs[tid][2] = f.z - o4.z;
    }
    float zp = g_zpart[bp * ZF + tid];
    float w0 = Ws1[0 * 128 + tid], w1 = Ws1[1 * 128 + tid], w2 = Ws1[2 * 128 + tid];
    __syncthreads();

    // layer 1: h1 = relu(x0*w0 + x1*w1 + x2*w2 + zpart)
#pragma unroll
    for (int k = 0; k < KS; ++k) {
        float a = fmaf(xs[k][2], w2, fmaf(xs[k][1], w1, fmaf(xs[k][0], w0, zp)));
        h1s[k * 129 + tid] = fmaxf(a, 0.f);
    }
    __syncthreads();

    // layer 2: lane = k, warp = output-quarter (16 outputs each)
    {
        int k = tid & 31, oq = tid >> 5;
        float acc[16];
#pragma unroll
        for (int j = 0; j < 16; ++j) acc[j] = bs2[oq * 16 + j];
        const float* hrow = &h1s[k * 129];
#pragma unroll 8
        for (int i = 0; i < 128; ++i) {
            float hv = hrow[i];
            const float4* wp = (const float4*)(Ws2 + i * 64 + oq * 16);
            float4 wa = wp[0], wb = wp[1], wc = wp[2], wd = wp[3];
            acc[0]  = fmaf(hv, wa.x, acc[0]);  acc[1]  = fmaf(hv, wa.y, acc[1]);
            acc[2]  = fmaf(hv, wa.z, acc[2]);  acc[3]  = fmaf(hv, wa.w, acc[3]);
            acc[4]  = fmaf(hv, wb.x, acc[4]);  acc[5]  = fmaf(hv, wb.y, acc[5]);
            acc[6]  = fmaf(hv, wb.z, acc[6]);  acc[7]  = fmaf(hv, wb.w, acc[7]);
            acc[8]  = fmaf(hv, wc.x, acc[8]);  acc[9]  = fmaf(hv, wc.y, acc[9]);
            acc[10] = fmaf(hv, wc.z, acc[10]); acc[11] = fmaf(hv, wc.w, acc[11]);
            acc[12] = fmaf(hv, wd.x, acc[12]); acc[13] = fmaf(hv, wd.y, acc[13]);
            acc[14] = fmaf(hv, wd.z, acc[14]); acc[15] = fmaf(hv, wd.w, acc[15]);
        }
#pragma unroll
        for (int j = 0; j < 16; ++j) h2s[k * 68 + oq * 16 + j] = fmaxf(acc[j], 0.f);
    }
    __syncthreads();

    // layer 3: 96 threads, (k,d)
    if (tid < 96) {
        int k = tid / 3, d = tid % 3;
        float a = bs3[d];
#pragma unroll 16
        for (int i = 0; i < 64; ++i) a = fmaf(h2s[k * 68 + i], Ws3[i * 3 + d], a);
        g_estim[(bp * KS + k) * 3 + d] = a;
    }
}

// insertion into sorted 4-element top list
#define INS4(s, id, s0, s1, s2, s3, i0, i1, i2, i3)             \
    if ((s) < (s3)) {                                           \
        if ((s) < (s2)) {                                       \
            (s3) = (s2); (i3) = (i2);                           \
            if ((s) < (s1)) {                                   \
                (s2) = (s1); (i2) = (i1);                       \
                if ((s) < (s0)) { (s1) = (s0); (i1) = (i0); (s0) = (s); (i0) = (id); } \
                else { (s1) = (s); (i1) = (id); }               \
            } else { (s2) = (s); (i2) = (id); }                 \
        } else { (s3) = (s); (i3) = (id); }                     \
    }

// ---------------- K4: KNN2 top-4 + ground score + loss partials ----------------
__global__ __launch_bounds__(256) void k4_knn2() {
    int bp = blockIdx.x;
    int b = bp >> 7;
    int tid = threadIdx.x, lane = tid & 31, w = tid >> 5;   // 8 warps
    __shared__ float4 buf[2048];                 // 32 KB tile
    __shared__ float  cs[8][32][4];
    __shared__ int    ci[8][32][4];

    float4 f = g_fpts[bp * KS + lane];           // lane = query k
    float s0 = finf(), s1 = finf(), s2 = finf(), s3 = finf();
    int   i0 = 0, i1 = 0, i2 = 0, i3 = 0;

    for (int t0 = 0; t0 < MM; t0 += 2048) {
        int n = min(2048, MM - t0);
        __syncthreads();
        for (int j = tid; j < n; j += 256) buf[j] = g_clean4[b * MM + t0 + j];
        __syncthreads();
        int chunk = (n + 7) >> 3;
        int start = w * chunk;
        int end = min(start + chunk, n);
#pragma unroll 4
        for (int r = start; r < end; ++r) {
            float4 v = buf[r];                   // broadcast LDS.128
            float dot = fmaf(f.z, v.z, fmaf(f.y, v.y, f.x * v.x));
            float s = fmaf(dot, -2.0f, v.w);     // d2 - |q|^2
            int id = t0 + r;
            INS4(s, id, s0, s1, s2, s3, i0, i1, i2, i3);
        }
    }
    cs[w][lane][0] = s0; cs[w][lane][1] = s1; cs[w][lane][2] = s2; cs[w][lane][3] = s3;
    ci[w][lane][0] = i0; ci[w][lane][1] = i1; ci[w][lane][2] = i2; ci[w][lane][3] = i3;
    __syncthreads();

    if (w == 0) {
        float b0 = finf(), b1 = finf(), b2 = finf(), b3 = finf();
        int   j0 = 0, j1 = 0, j2 = 0, j3 = 0;
#pragma unroll
        for (int ww = 0; ww < 8; ++ww)
#pragma unroll
            for (int jj = 0; jj < 4; ++jj) {
                float s = cs[ww][lane][jj];
                int id = ci[ww][lane][jj];
                INS4(s, id, b0, b1, b2, b3, j0, j1, j2, j3);
            }
        float4 c0 = g_clean4[b * MM + j0];
        float4 c1 = g_clean4[b * MM + j1];
        float4 c2 = g_clean4[b * MM + j2];
        float4 c3 = g_clean4[b * MM + j3];
        float gx = (c0.x + c1.x + c2.x + c3.x) * 0.25f - f.x;
        float gy = (c0.y + c1.y + c2.y + c3.y) * 0.25f - f.y;
        float gz = (c0.z + c1.z + c2.z + c3.z) * 0.25f - f.z;
        const float* e = g_estim + (bp * KS + lane) * 3;
        float d0 = e[0] - gx, d1 = e[1] - gy, d2v = e[2] - gz;
        float err = fmaf(d0, d0, fmaf(d1, d1, d2v * d2v));
#pragma unroll
        for (int off = 16; off > 0; off >>= 1)
            err += __shfl_xor_sync(0xFFFFFFFFu, err, off);
        if (lane == 0) g_partial[bp] = err;
    }
}

// ---------------- K5: deterministic final reduce ----------------
__global__ void k5_reduce(float* __restrict__ out) {
    __shared__ float sm[512];
    int tid = threadIdx.x;
    sm[tid] = g_partial[tid];
    __syncthreads();
#pragma unroll
    for (int s = 256; s > 0; s >>= 1) {
        if (tid < s) sm[tid] += sm[tid + s];
        __syncthreads();
    }
    // loss = 0.5 * mean_{B*P*K}( sum_d (.)^2 / SIGMA ) = total * 0.5*100/16384
    if (tid == 0) out[0] = sm[0] * (50.0f / 16384.0f);
}

extern "C" void kernel_launch(void* const* d_in, const int* in_sizes, int n_in,
                              void* d_out, int out_size) {
    const float* noisy = (const float*)d_in[0];
    const float* clean = (const float*)d_in[1];
    const int*   sidx  = (const int*)d_in[2];
    const float* Wf1 = (const float*)d_in[3];
    const float* bf1 = (const float*)d_in[4];
    const float* Wf2 = (const float*)d_in[5];
    const float* bf2 = (const float*)d_in[6];
    const float* Ws1 = (const float*)d_in[7];
    const float* bs1 = (const float*)d_in[8];
    const float* Ws2 = (const float*)d_in[9];
    const float* bs2 = (const float*)d_in[10];
    const float* Ws3 = (const float*)d_in[11];
    const float* bs3 = (const float*)d_in[12];
    float* out = (float*)d_out;

    k0_pack<<<(BB * NN + 255) / 256, 256>>>(noisy, clean);
    k1_feat<<<BB * PP, 128>>>(noisy, sidx, Wf1, bf1, Wf2, bf2, Ws1, bs1);
    k2_knn1<<<BB * PP, 256>>>();
    k3_mlp<<<BB * PP, 128>>>(Ws1, Ws2, bs2, Ws3, bs3);
    k4_knn2<<<BB * PP, 256>>>();
    k5_reduce<<<1, 512>>>(out);
}